// round 1
// baseline (speedup 1.0000x reference)
#include <cuda_runtime.h>
#include <math.h>

// BoundaryLoss collapses analytically:
//   dist_map = min(dist_to_zero_set, dist_to_nonzero_set) == 0 everywhere
//   (every pixel is in one of the two sets, distance to own set is 0)
//   => w = exp(0) = 1, max(w) = 1, final_weight = 1 + THETA = 6 (constant)
//   => out = 6 * mean( softplus(pred) - pred*target )
//
// N = 8*1*256*256 = 524288 floats each for pred/target.

#define N_ELEMS   524288
#define N_VEC4    (N_ELEMS / 4)      // 131072
#define BLOCKS    512
#define THREADS   256                // BLOCKS*THREADS == N_VEC4 exactly

__device__ float g_partials[BLOCKS];

__device__ __forceinline__ float softplus_f(float x) {
    // logaddexp(0, x) = max(x,0) + log1p(exp(-|x|))
    return fmaxf(x, 0.0f) + log1pf(__expf(-fabsf(x)));
}

__global__ __launch_bounds__(THREADS) void bce_partial_kernel(
    const float* __restrict__ pred, const float* __restrict__ target)
{
    const int gid = blockIdx.x * THREADS + threadIdx.x;  // one float4 per thread

    const float4 p = reinterpret_cast<const float4*>(pred)[gid];
    const float4 t = reinterpret_cast<const float4*>(target)[gid];

    float s = (softplus_f(p.x) - p.x * t.x)
            + (softplus_f(p.y) - p.y * t.y)
            + (softplus_f(p.z) - p.z * t.z)
            + (softplus_f(p.w) - p.w * t.w);

    // warp reduce
    #pragma unroll
    for (int off = 16; off > 0; off >>= 1)
        s += __shfl_down_sync(0xFFFFFFFFu, s, off);

    __shared__ float warp_sums[THREADS / 32];
    const int lane = threadIdx.x & 31;
    const int wid  = threadIdx.x >> 5;
    if (lane == 0) warp_sums[wid] = s;
    __syncthreads();

    if (wid == 0) {
        float v = (lane < THREADS / 32) ? warp_sums[lane] : 0.0f;
        #pragma unroll
        for (int off = 4; off > 0; off >>= 1)
            v += __shfl_down_sync(0xFFFFFFFFu, v, off);
        if (lane == 0) g_partials[blockIdx.x] = v;
    }
}

__global__ __launch_bounds__(512) void final_reduce_kernel(float* __restrict__ out)
{
    float s = g_partials[threadIdx.x];  // 512 threads == BLOCKS

    #pragma unroll
    for (int off = 16; off > 0; off >>= 1)
        s += __shfl_down_sync(0xFFFFFFFFu, s, off);

    __shared__ float warp_sums[16];
    const int lane = threadIdx.x & 31;
    const int wid  = threadIdx.x >> 5;
    if (lane == 0) warp_sums[wid] = s;
    __syncthreads();

    if (wid == 0) {
        float v = (lane < 16) ? warp_sums[lane] : 0.0f;
        #pragma unroll
        for (int off = 8; off > 0; off >>= 1)
            v += __shfl_down_sync(0xFFFFFFFFu, v, off);
        if (lane == 0)
            out[0] = v * (6.0f / (float)N_ELEMS);
    }
}

extern "C" void kernel_launch(void* const* d_in, const int* in_sizes, int n_in,
                              void* d_out, int out_size)
{
    const float* pred   = (const float*)d_in[0];
    const float* target = (const float*)d_in[1];
    float* out = (float*)d_out;

    bce_partial_kernel<<<BLOCKS, THREADS>>>(pred, target);
    final_reduce_kernel<<<1, 512>>>(out);
}